// round 11
// baseline (speedup 1.0000x reference)
#include <cuda_runtime.h>
#include <cuda_fp16.h>

#define DM 256
#define NH 4
#define DH 64
#define BB 4
#define TT 512
#define SS 512
#define BHN 16
#define MM 2048
#define PSZ (MM * DM)

// Scratch (no allocs -> device globals)
__device__ unsigned int g_Qh[BHN * TT * 32];  // half2 [bh][t][d/2]
__device__ unsigned int g_Kh[BHN * SS * 32];  // half2 [bh][s][d/2]
__device__ float g_V[BHN * SS * DH];          // f32   [bh][s][d]
__device__ float g_att[BB * TT * DM];         // attended [b][t][h*64+d]
__device__ float g_P[2 * PSZ];                // split-K partials for out proj

// ---- packed helpers -------------------------------------------------------
__device__ __forceinline__ unsigned long long pack2(float x, float y) {
    unsigned long long r;
    asm("mov.b64 %0, {%1, %2};" : "=l"(r) : "f"(x), "f"(y));
    return r;
}
__device__ __forceinline__ float2 unpack2(unsigned long long v) {
    float2 r;
    asm("mov.b64 {%0, %1}, %2;" : "=f"(r.x), "=f"(r.y) : "l"(v));
    return r;
}
__device__ __forceinline__ unsigned long long fma2(unsigned long long a,
                                                   unsigned long long b,
                                                   unsigned long long c) {
    unsigned long long d;
    asm("fma.rn.f32x2 %0, %1, %2, %3;" : "=l"(d) : "l"(a), "l"(b), "l"(c));
    return d;
}
__device__ __forceinline__ unsigned int htanh2(unsigned int x) {
    unsigned int y;
    asm("tanh.approx.f16x2 %0, %1;" : "=r"(y) : "r"(x));
    return y;
}
__device__ __forceinline__ unsigned int hadd2u(unsigned int a, unsigned int b) {
    unsigned int y;
    asm("add.rn.f16x2 %0, %1, %2;" : "=r"(y) : "r"(a), "r"(b));
    return y;
}
__device__ __forceinline__ unsigned int hmul2u(unsigned int a, unsigned int b) {
    unsigned int y;
    asm("mul.rn.f16x2 %0, %1, %2;" : "=r"(y) : "r"(a), "r"(b));
    return y;
}
__device__ __forceinline__ unsigned int hfma2u(unsigned int a, unsigned int b, unsigned int c) {
    unsigned int y;
    asm("fma.rn.f16x2 %0, %1, %2, %3;" : "=r"(y) : "r"(a), "r"(b), "r"(c));
    return y;
}
__device__ __forceinline__ float2 h2f2(unsigned int h) {
    __half2 v = *reinterpret_cast<__half2*>(&h);
    return __half22float2(v);
}

// 8-element weighted tanh dot, fp16 product chain (len 4), fp32 result.
__device__ __forceinline__ float dot8h(uint4 q, uint4 k, uint4 vah) {
    unsigned int t0 = htanh2(hadd2u(q.x, k.x));
    unsigned int t1 = htanh2(hadd2u(q.y, k.y));
    unsigned int t2 = htanh2(hadd2u(q.z, k.z));
    unsigned int t3 = htanh2(hadd2u(q.w, k.w));
    unsigned int c = hmul2u(vah.x, t0);
    c = hfma2u(vah.y, t1, c);
    c = hfma2u(vah.z, t2, c);
    c = hfma2u(vah.w, t3, c);
    float2 f = h2f2(c);
    return f.x + f.y;
}

// ---------------------------------------------------------------------------
// GEMM v2 (crossbar-relieved): 128m x 64n tile, 256 thr, 8m x 4n micro.
// Accumulators hold (m, m+1) pairs -> A read as packed ulonglong2 (no packs);
// only W needs 4 pack2/kk. 3 LDS.128 per 16 fma2 -> FMA-bound.
// mode_base 0 (proj): z = 0/1/2 -> g_Qh/g_Kh/g_V, full K=256.
// mode_base 3 (out) : z = kh (split-K=2), A=g_att, W via q_in slot -> g_P[kh].
// ---------------------------------------------------------------------------
__global__ __launch_bounds__(256) void gemm_kernel(const float* __restrict__ q_in,
                                                   const float* __restrict__ k_in,
                                                   const float* __restrict__ v_in,
                                                   const float* __restrict__ w_q,
                                                   const float* __restrict__ w_k,
                                                   const float* __restrict__ w_v,
                                                   int mode_base) {
    __shared__ float Ast[2][16 * 132];   // [k][m], pitch 132
    __shared__ float Wst[2][16 * 68];    // [k][n], pitch 68

    const int z = blockIdx.z;
    int kh = 0, mode;
    const float *A, *W;
    if (mode_base == 3) {
        mode = 3; kh = z; A = g_att; W = q_in;   // q_in slot carries w_o
    } else {
        mode = z;
        A = (z == 0) ? q_in : (z == 1) ? k_in : v_in;
        W = (z == 0) ? w_q : (z == 1) ? w_k : w_v;
    }
    const int KCH = (mode == 3) ? 8 : 16;        // 16-k chunks

    const int m0 = blockIdx.x * 128;
    const int n0 = blockIdx.y * 64;
    const int tid = threadIdx.x;
    const int tx = tid & 15;     // n/4
    const int tyy = tid >> 4;    // m/8 (0..15)

    const int lrA = tid >> 1;           // 0..127
    const int lcA = (tid & 1) * 8;      // 0 or 8
    const int lrW = tid >> 2;           // 0..63
    const int lcW = (tid & 3) * 4;      // 0..12
    const float* Aptr = A + (size_t)(m0 + lrA) * DM + kh * 128 + lcA;
    const float* Wptr = W + (size_t)(n0 + lrW) * DM + kh * 128 + lcW;

    unsigned long long acc[4][4];       // [m-pair][n]
#pragma unroll
    for (int i = 0; i < 4; i++)
#pragma unroll
        for (int j = 0; j < 4; j++) acc[i][j] = 0ull;

    // prologue: chunk0 -> buf0; prefetch chunk1
    float4 ra0 = *(const float4*)Aptr;
    float4 ra1 = *(const float4*)(Aptr + 4);
    float4 rw = *(const float4*)Wptr;
#pragma unroll
    for (int j = 0; j < 4; j++) {
        Ast[0][(lcA + j) * 132 + lrA] = ((const float*)&ra0)[j];
        Ast[0][(lcA + j + 4) * 132 + lrA] = ((const float*)&ra1)[j];
        Wst[0][(lcW + j) * 68 + lrW] = ((const float*)&rw)[j];
    }
    ra0 = *(const float4*)(Aptr + 16);
    ra1 = *(const float4*)(Aptr + 20);
    rw = *(const float4*)(Wptr + 16);

#pragma unroll 1
    for (int c = 0; c < KCH; c++) {
        const int p = c & 1;
        __syncthreads();
        if (c < KCH - 1) {
#pragma unroll
            for (int j = 0; j < 4; j++) {
                Ast[p ^ 1][(lcA + j) * 132 + lrA] = ((const float*)&ra0)[j];
                Ast[p ^ 1][(lcA + j + 4) * 132 + lrA] = ((const float*)&ra1)[j];
                Wst[p ^ 1][(lcW + j) * 68 + lrW] = ((const float*)&rw)[j];
            }
        }
        if (c < KCH - 2) {
            ra0 = *(const float4*)(Aptr + (c + 2) * 16);
            ra1 = *(const float4*)(Aptr + (c + 2) * 16 + 4);
            rw = *(const float4*)(Wptr + (c + 2) * 16);
        }
#pragma unroll
        for (int kk = 0; kk < 16; kk++) {
            ulonglong2 aA = *(const ulonglong2*)&Ast[p][kk * 132 + tyy * 8];      // (m0,m1),(m2,m3)
            ulonglong2 aB = *(const ulonglong2*)&Ast[p][kk * 132 + tyy * 8 + 4];  // (m4,m5),(m6,m7)
            float4 w4 = *(const float4*)&Wst[p][kk * 68 + tx * 4];
            unsigned long long wd0 = pack2(w4.x, w4.x);
            unsigned long long wd1 = pack2(w4.y, w4.y);
            unsigned long long wd2 = pack2(w4.z, w4.z);
            unsigned long long wd3 = pack2(w4.w, w4.w);
            acc[0][0] = fma2(aA.x, wd0, acc[0][0]); acc[0][1] = fma2(aA.x, wd1, acc[0][1]);
            acc[0][2] = fma2(aA.x, wd2, acc[0][2]); acc[0][3] = fma2(aA.x, wd3, acc[0][3]);
            acc[1][0] = fma2(aA.y, wd0, acc[1][0]); acc[1][1] = fma2(aA.y, wd1, acc[1][1]);
            acc[1][2] = fma2(aA.y, wd2, acc[1][2]); acc[1][3] = fma2(aA.y, wd3, acc[1][3]);
            acc[2][0] = fma2(aB.x, wd0, acc[2][0]); acc[2][1] = fma2(aB.x, wd1, acc[2][1]);
            acc[2][2] = fma2(aB.x, wd2, acc[2][2]); acc[2][3] = fma2(aB.x, wd3, acc[2][3]);
            acc[3][0] = fma2(aB.y, wd0, acc[3][0]); acc[3][1] = fma2(aB.y, wd1, acc[3][1]);
            acc[3][2] = fma2(aB.y, wd2, acc[3][2]); acc[3][3] = fma2(aB.y, wd3, acc[3][3]);
        }
    }

    // epilogues: row i (0..7) -> acc[i>>1][n], lo/hi half by i&1
    const int hh = n0 >> 6;
#pragma unroll
    for (int i = 0; i < 8; i++) {
        const int pr = i >> 1, sel = i & 1;
        float v[4];
#pragma unroll
        for (int n = 0; n < 4; n++) {
            float2 f = unpack2(acc[pr][n]);
            v[n] = sel ? f.y : f.x;
        }
        int m = m0 + tyy * 8 + i;
        if (mode <= 1) {
            unsigned int* dst = (mode == 0) ? g_Qh : g_Kh;
            int bb = m >> 9, t = m & 511;
            __half2 h0 = __floats2half2_rn(v[0], v[1]);
            __half2 h1 = __floats2half2_rn(v[2], v[3]);
            uint2 u = make_uint2(*(unsigned int*)&h0, *(unsigned int*)&h1);
            *(uint2*)&dst[((size_t)(bb * NH + hh) * TT + t) * 32 + tx * 2] = u;
        } else if (mode == 2) {
            int bb = m >> 9, t = m & 511;
            *(float4*)&g_V[((size_t)(bb * NH + hh) * TT + t) * DH + tx * 4] =
                make_float4(v[0], v[1], v[2], v[3]);
        } else {
            float* P = g_P + (size_t)kh * PSZ;
            *(float4*)&P[(size_t)m * DM + n0 + tx * 4] =
                make_float4(v[0], v[1], v[2], v[3]);
        }
    }
}

// Combine split-K partials for output projection: out = g_P[0] + g_P[1].
__global__ __launch_bounds__(256) void combine_out(float* __restrict__ out) {
    const int m = blockIdx.x * 8 + (threadIdx.x >> 5);
    const int n = (threadIdx.x & 31) * 8;
    const float* P0 = g_P + (size_t)m * DM + n;
    const float* P1 = P0 + PSZ;
    float4 a0 = *(const float4*)P0;
    float4 a1 = *(const float4*)(P0 + 4);
    float4 b0 = *(const float4*)P1;
    float4 b1 = *(const float4*)(P1 + 4);
    float* o = out + (size_t)m * DM + n;
    *(float4*)o = make_float4(a0.x + b0.x, a0.y + b0.y, a0.z + b0.z, a0.w + b0.w);
    *(float4*)(o + 4) = make_float4(a1.x + b1.x, a1.y + b1.y, a1.z + b1.z, a1.w + b1.w);
}

// ---------------------------------------------------------------------------
// Fused scores(tanh, h16 chain) + softmax + AV (unchanged from R10 best).
// ---------------------------------------------------------------------------
#define SCP 516
__global__ __launch_bounds__(256, 2) void attn_fused_kernel(const float* __restrict__ v_a,
                                                            float* __restrict__ attn) {
    extern __shared__ float sm[];
    float* sc = sm;              // 32 * 516
    float* Bs = sm + 32 * SCP;   // 32 * 68

    __shared__ unsigned int vas_h[32];

    const int bh = blockIdx.x;
    const int t0 = blockIdx.y * 32;
    const int h = bh & 3;
    const int tid = threadIdx.x;
    const int lane = tid & 31;
    const int w = tid >> 5;

    if (tid < 16) {
        float4 v = ((const float4*)(v_a + h * DH))[tid];
        __half2 h0 = __floats2half2_rn(v.x, v.y);
        __half2 h1 = __floats2half2_rn(v.z, v.w);
        vas_h[tid * 2] = *(unsigned int*)&h0;
        vas_h[tid * 2 + 1] = *(unsigned int*)&h1;
    }
    __syncthreads();

    // ---- Phase 1: scores -> sc (8 s-streams per warp, h16 chains) -------------
    {
        uint4 qreg[8];
        const uint4* qg = (const uint4*)(g_Qh + ((size_t)bh * TT + t0 + lane) * 32);
#pragma unroll
        for (int i = 0; i < 8; i++) qreg[i] = qg[i];

#pragma unroll 1
        for (int g = 0; g < 8; g++) {
            const int sl = w * 64 + g * 8;
            const uint4* K0 = (const uint4*)(g_Kh + ((size_t)bh * SS + sl) * 32);
            const uint4* K1 = K0 + 8;
            const uint4* K2 = K0 + 16;
            const uint4* K3 = K0 + 24;
            const uint4* K4 = K0 + 32;
            const uint4* K5 = K0 + 40;
            const uint4* K6 = K0 + 48;
            const uint4* K7 = K0 + 56;
            float a0 = 0.f, a1 = 0.f, a2 = 0.f, a3 = 0.f;
            float a4 = 0.f, a5 = 0.f, a6 = 0.f, a7 = 0.f;
#pragma unroll
            for (int i = 0; i < 8; i++) {
                uint4 vah = *(const uint4*)&vas_h[i * 4];
                uint4 q = qreg[i];
                a0 += dot8h(q, K0[i], vah);
                a1 += dot8h(q, K1[i], vah);
                a2 += dot8h(q, K2[i], vah);
                a3 += dot8h(q, K3[i], vah);
                a4 += dot8h(q, K4[i], vah);
                a5 += dot8h(q, K5[i], vah);
                a6 += dot8h(q, K6[i], vah);
                a7 += dot8h(q, K7[i], vah);
            }
            *(float4*)&sc[lane * SCP + sl] =
                make_float4(a0 * 0.125f, a1 * 0.125f, a2 * 0.125f, a3 * 0.125f);
            *(float4*)&sc[lane * SCP + sl + 4] =
                make_float4(a4 * 0.125f, a5 * 0.125f, a6 * 0.125f, a7 * 0.125f);
        }
    }
    __syncthreads();

    // ---- Phase 2: softmax -------------------------------------------------------
#pragma unroll 1
    for (int q = 0; q < 4; q++) {
        int r = w * 4 + q;
        float4* row = (float4*)&sc[r * SCP];
        float4 x0 = row[lane], x1 = row[lane + 32], x2 = row[lane + 64], x3 = row[lane + 96];
        float m = fmaxf(fmaxf(fmaxf(x0.x, x0.y), fmaxf(x0.z, x0.w)),
                        fmaxf(fmaxf(x1.x, x1.y), fmaxf(x1.z, x1.w)));
        m = fmaxf(m, fmaxf(fmaxf(fmaxf(x2.x, x2.y), fmaxf(x2.z, x2.w)),
                           fmaxf(fmaxf(x3.x, x3.y), fmaxf(x3.z, x3.w))));
#pragma unroll
        for (int o = 16; o; o >>= 1) m = fmaxf(m, __shfl_xor_sync(0xffffffffu, m, o));
        x0.x = __expf(x0.x - m); x0.y = __expf(x0.y - m); x0.z = __expf(x0.z - m); x0.w = __expf(x0.w - m);
        x1.x = __expf(x1.x - m); x1.y = __expf(x1.y - m); x1.z = __expf(x1.z - m); x1.w = __expf(x1.w - m);
        x2.x = __expf(x2.x - m); x2.y = __expf(x2.y - m); x2.z = __expf(x2.z - m); x2.w = __expf(x2.w - m);
        x3.x = __expf(x3.x - m); x3.y = __expf(x3.y - m); x3.z = __expf(x3.z - m); x3.w = __expf(x3.w - m);
        float s = (x0.x + x0.y + x0.z + x0.w) + (x1.x + x1.y + x1.z + x1.w)
                + (x2.x + x2.y + x2.z + x2.w) + (x3.x + x3.y + x3.z + x3.w);
#pragma unroll
        for (int o = 16; o; o >>= 1) s += __shfl_xor_sync(0xffffffffu, s, o);
        float inv = 1.0f / s;
        x0.x *= inv; x0.y *= inv; x0.z *= inv; x0.w *= inv;
        x1.x *= inv; x1.y *= inv; x1.z *= inv; x1.w *= inv;
        x2.x *= inv; x2.y *= inv; x2.z *= inv; x2.w *= inv;
        x3.x *= inv; x3.y *= inv; x3.z *= inv; x3.w *= inv;
        row[lane] = x0; row[lane + 32] = x1; row[lane + 64] = x2; row[lane + 96] = x3;
    }
    __syncthreads();

    // ---- Phase 3: write attn -----------------------------------------------------
    {
        float* arow = attn + ((size_t)bh * TT + t0) * SS;
        for (int i = tid; i < 32 * 128; i += 256) {
            int r = i >> 7, c = i & 127;
            *(float4*)&arow[(size_t)r * SS + c * 4] = *(const float4*)&sc[r * SCP + c * 4];
        }
    }

    // ---- Phase 4: AV ---------------------------------------------------------------
    const float* Vg = g_V + (size_t)bh * SS * DH;
    const int tx = tid & 15;
    const int tyy = tid >> 4;
    unsigned long long acc[2][2];
    acc[0][0] = acc[0][1] = acc[1][0] = acc[1][1] = 0ull;

#pragma unroll 1
    for (int s0 = 0; s0 < SS; s0 += 32) {
        __syncthreads();
        for (int i = tid; i < 512; i += 256) {
            int rr = i >> 4, cc = i & 15;
            *(float4*)&Bs[rr * 68 + cc * 4] = *(const float4*)&Vg[(size_t)(s0 + rr) * DH + cc * 4];
        }
        __syncthreads();
#pragma unroll 8
        for (int kk = 0; kk < 32; kk++) {
            ulonglong2 b2 = *(const ulonglong2*)&Bs[kk * 68 + tx * 4];
            float a0 = sc[(size_t)(tyy * 2) * SCP + s0 + kk];
            float a1 = sc[(size_t)(tyy * 2 + 1) * SCP + s0 + kk];
            unsigned long long aa;
            aa = pack2(a0, a0); acc[0][0] = fma2(aa, b2.x, acc[0][0]); acc[0][1] = fma2(aa, b2.y, acc[0][1]);
            aa = pack2(a1, a1); acc[1][0] = fma2(aa, b2.x, acc[1][0]); acc[1][1] = fma2(aa, b2.y, acc[1][1]);
        }
    }

    {
        const int b = bh >> 2;
#pragma unroll
        for (int i = 0; i < 2; i++) {
            int t = t0 + tyy * 2 + i;
            float2 c01 = unpack2(acc[i][0]);
            float2 c23 = unpack2(acc[i][1]);
            *(float4*)&g_att[((size_t)(b * TT + t)) * DM + h * DH + tx * 4] =
                make_float4(c01.x, c01.y, c23.x, c23.y);
        }
    }
}

// ---------------------------------------------------------------------------
extern "C" void kernel_launch(void* const* d_in, const int* in_sizes, int n_in,
                              void* d_out, int out_size) {
    const float* query = (const float*)d_in[0];
    const float* key   = (const float*)d_in[1];
    const float* value = (const float*)d_in[2];
    const float* w_q   = (const float*)d_in[3];
    const float* w_k   = (const float*)d_in[4];
    const float* w_v   = (const float*)d_in[5];
    const float* v_a   = (const float*)d_in[6];
    const float* w_o   = (const float*)d_in[7];

    float* out  = (float*)d_out;
    float* attn = out + (size_t)BB * TT * DM;

    // Q/K/V projections: 128x64 tiles, grid 192
    gemm_kernel<<<dim3(16, 4, 3), 256>>>(query, key, value, w_q, w_k, w_v, 0);

    // fused additive-attention (scores + softmax + AV)
    const int dyn = (32 * SCP + 32 * 68) * sizeof(float);   // ~74.8 KB
    cudaFuncSetAttribute(attn_fused_kernel,
                         cudaFuncAttributeMaxDynamicSharedMemorySize, dyn);
    attn_fused_kernel<<<dim3(BHN, TT / 32), 256, dyn>>>(v_a, attn);

    // output projection: split-K=2 (grid 128) + combine
    gemm_kernel<<<dim3(16, 4, 2), 256>>>(w_o, nullptr, nullptr, nullptr, nullptr, nullptr, 3);
    combine_out<<<256, 256>>>(out);
}

// round 12
// speedup vs baseline: 1.1981x; 1.1981x over previous
#include <cuda_runtime.h>
#include <cuda_fp16.h>
#include <mma.h>
using namespace nvcuda;

#define DM 256
#define NH 4
#define DH 64
#define BB 4
#define TT 512
#define SS 512
#define BHN 16

// Scratch (no allocs -> device globals)
__device__ unsigned int g_Qh[BHN * TT * 32];  // half2 [bh][t][d/2]
__device__ unsigned int g_Kh[BHN * SS * 32];  // half2 [bh][s][d/2]
__device__ float g_V[BHN * SS * DH];          // f32   [bh][s][d]
__device__ __half g_attH[BB * TT * DM];       // attended, fp16 [b][t][h*64+d]

// ---- packed helpers -------------------------------------------------------
__device__ __forceinline__ unsigned long long pack2(float x, float y) {
    unsigned long long r;
    asm("mov.b64 %0, {%1, %2};" : "=l"(r) : "f"(x), "f"(y));
    return r;
}
__device__ __forceinline__ float2 unpack2(unsigned long long v) {
    float2 r;
    asm("mov.b64 {%0, %1}, %2;" : "=f"(r.x), "=f"(r.y) : "l"(v));
    return r;
}
__device__ __forceinline__ unsigned long long fma2(unsigned long long a,
                                                   unsigned long long b,
                                                   unsigned long long c) {
    unsigned long long d;
    asm("fma.rn.f32x2 %0, %1, %2, %3;" : "=l"(d) : "l"(a), "l"(b), "l"(c));
    return d;
}
__device__ __forceinline__ unsigned int htanh2(unsigned int x) {
    unsigned int y;
    asm("tanh.approx.f16x2 %0, %1;" : "=r"(y) : "r"(x));
    return y;
}
__device__ __forceinline__ unsigned int hadd2u(unsigned int a, unsigned int b) {
    unsigned int y;
    asm("add.rn.f16x2 %0, %1, %2;" : "=r"(y) : "r"(a), "r"(b));
    return y;
}
__device__ __forceinline__ unsigned int hmul2u(unsigned int a, unsigned int b) {
    unsigned int y;
    asm("mul.rn.f16x2 %0, %1, %2;" : "=r"(y) : "r"(a), "r"(b));
    return y;
}
__device__ __forceinline__ unsigned int hfma2u(unsigned int a, unsigned int b, unsigned int c) {
    unsigned int y;
    asm("fma.rn.f16x2 %0, %1, %2, %3;" : "=r"(y) : "r"(a), "r"(b), "r"(c));
    return y;
}
__device__ __forceinline__ float2 h2f2(unsigned int h) {
    __half2 v = *reinterpret_cast<__half2*>(&h);
    return __half22float2(v);
}

// 8-element weighted tanh dot, fp16 product chain (len 4), fp32 result.
__device__ __forceinline__ float dot8h(uint4 q, uint4 k, uint4 vah) {
    unsigned int t0 = htanh2(hadd2u(q.x, k.x));
    unsigned int t1 = htanh2(hadd2u(q.y, k.y));
    unsigned int t2 = htanh2(hadd2u(q.z, k.z));
    unsigned int t3 = htanh2(hadd2u(q.w, k.w));
    unsigned int c = hmul2u(vah.x, t0);
    c = hfma2u(vah.y, t1, c);
    c = hfma2u(vah.z, t2, c);
    c = hfma2u(vah.w, t3, c);
    float2 f = h2f2(c);
    return f.x + f.y;
}

// ---------------------------------------------------------------------------
// Tensor-core projection GEMM: C[m][n] = sum_k A[m][k]*W[n][k], fp16 in,
// f32 accumulate. 64x64 tile, 256 thr = 8 warps (4m x 2n), warp 16m x 32n.
// z = 0/1/2 -> g_Qh (h16), g_Kh (h16), g_V (f32).
// ---------------------------------------------------------------------------
__global__ __launch_bounds__(256) void hgemm_proj(const float* __restrict__ q_in,
                                                  const float* __restrict__ k_in,
                                                  const float* __restrict__ v_in,
                                                  const float* __restrict__ w_q,
                                                  const float* __restrict__ w_k,
                                                  const float* __restrict__ w_v) {
    __shared__ __align__(32) __half Ah[64 * 24];   // [m][k], pitch 24 halves
    __shared__ __align__(32) __half Bh[64 * 24];   // [n][k], pitch 24
    __shared__ __align__(16) float Cst[64 * 72];   // [m][n], pitch 72

    const int mode = blockIdx.z;
    const float* A = (mode == 0) ? q_in : (mode == 1) ? k_in : v_in;
    const float* W = (mode == 0) ? w_q : (mode == 1) ? w_k : w_v;

    const int m0 = blockIdx.x * 64;
    const int n0 = blockIdx.y * 64;
    const int tid = threadIdx.x;
    const int w = tid >> 5;
    const int wm = w >> 1;        // 0..3
    const int wn = w & 1;         // 0..1
    const int r = tid >> 2;       // 0..63
    const int c = (tid & 3) * 4;  // 0,4,8,12

    wmma::fragment<wmma::accumulator, 16, 16, 16, float> c0, c1;
    wmma::fill_fragment(c0, 0.0f);
    wmma::fill_fragment(c1, 0.0f);

    float4 ra = *(const float4*)&A[(size_t)(m0 + r) * DM + c];
    float4 rw = *(const float4*)&W[(size_t)(n0 + r) * DM + c];

#pragma unroll 1
    for (int kc = 0; kc < 16; kc++) {
        {
            __half2 a0 = __floats2half2_rn(ra.x, ra.y), a1 = __floats2half2_rn(ra.z, ra.w);
            __half2 b0 = __floats2half2_rn(rw.x, rw.y), b1 = __floats2half2_rn(rw.z, rw.w);
            *(__half2*)&Ah[r * 24 + c] = a0;
            *(__half2*)&Ah[r * 24 + c + 2] = a1;
            *(__half2*)&Bh[r * 24 + c] = b0;
            *(__half2*)&Bh[r * 24 + c + 2] = b1;
        }
        __syncthreads();
        if (kc < 15) {
            ra = *(const float4*)&A[(size_t)(m0 + r) * DM + (kc + 1) * 16 + c];
            rw = *(const float4*)&W[(size_t)(n0 + r) * DM + (kc + 1) * 16 + c];
        }
        {
            wmma::fragment<wmma::matrix_a, 16, 16, 16, __half, wmma::row_major> af;
            wmma::fragment<wmma::matrix_b, 16, 16, 16, __half, wmma::col_major> bf0, bf1;
            wmma::load_matrix_sync(af, &Ah[wm * 16 * 24], 24);
            wmma::load_matrix_sync(bf0, &Bh[(wn * 32) * 24], 24);
            wmma::load_matrix_sync(bf1, &Bh[(wn * 32 + 16) * 24], 24);
            wmma::mma_sync(c0, af, bf0, c0);
            wmma::mma_sync(c1, af, bf1, c1);
        }
        __syncthreads();
    }

    wmma::store_matrix_sync(&Cst[(wm * 16) * 72 + wn * 32], c0, 72, wmma::mem_row_major);
    wmma::store_matrix_sync(&Cst[(wm * 16) * 72 + wn * 32 + 16], c1, 72, wmma::mem_row_major);
    __syncthreads();

    // epilogue scatter: thread = 4 rows x 4 cols
    const int tx = tid & 15;   // n/4
    const int ty = tid >> 4;   // m/4
    const int hh = n0 >> 6;
#pragma unroll
    for (int i = 0; i < 4; i++) {
        int m = m0 + ty * 4 + i;
        int bb = m >> 9, t = m & 511;
        float4 v = *(const float4*)&Cst[(ty * 4 + i) * 72 + tx * 4];
        if (mode <= 1) {
            unsigned int* dst = (mode == 0) ? g_Qh : g_Kh;
            __half2 h0 = __floats2half2_rn(v.x, v.y);
            __half2 h1 = __floats2half2_rn(v.z, v.w);
            uint2 u = make_uint2(*(unsigned int*)&h0, *(unsigned int*)&h1);
            *(uint2*)&dst[((size_t)(bb * NH + hh) * TT + t) * 32 + tx * 2] = u;
        } else {
            *(float4*)&g_V[((size_t)(bb * NH + hh) * TT + t) * DH + tx * 4] = v;
        }
    }
}

// ---------------------------------------------------------------------------
// Tensor-core output GEMM: out = g_attH (fp16) @ w_o.T, f32 accumulate.
// ---------------------------------------------------------------------------
__global__ __launch_bounds__(256) void hgemm_out(const float* __restrict__ w_o,
                                                 float* __restrict__ out) {
    __shared__ __align__(32) __half Ah[64 * 24];
    __shared__ __align__(32) __half Bh[64 * 24];
    __shared__ __align__(16) float Cst[64 * 72];

    const int m0 = blockIdx.x * 64;
    const int n0 = blockIdx.y * 64;
    const int tid = threadIdx.x;
    const int w = tid >> 5;
    const int wm = w >> 1;
    const int wn = w & 1;
    const int r = tid >> 2;
    const int c = (tid & 3) * 4;

    wmma::fragment<wmma::accumulator, 16, 16, 16, float> c0, c1;
    wmma::fill_fragment(c0, 0.0f);
    wmma::fill_fragment(c1, 0.0f);

    uint2 ra = *(const uint2*)&g_attH[(size_t)(m0 + r) * DM + c];
    float4 rw = *(const float4*)&w_o[(size_t)(n0 + r) * DM + c];

#pragma unroll 1
    for (int kc = 0; kc < 16; kc++) {
        {
            __half2 b0 = __floats2half2_rn(rw.x, rw.y), b1 = __floats2half2_rn(rw.z, rw.w);
            *(uint2*)&Ah[r * 24 + c] = ra;
            *(__half2*)&Bh[r * 24 + c] = b0;
            *(__half2*)&Bh[r * 24 + c + 2] = b1;
        }
        __syncthreads();
        if (kc < 15) {
            ra = *(const uint2*)&g_attH[(size_t)(m0 + r) * DM + (kc + 1) * 16 + c];
            rw = *(const float4*)&w_o[(size_t)(n0 + r) * DM + (kc + 1) * 16 + c];
        }
        {
            wmma::fragment<wmma::matrix_a, 16, 16, 16, __half, wmma::row_major> af;
            wmma::fragment<wmma::matrix_b, 16, 16, 16, __half, wmma::col_major> bf0, bf1;
            wmma::load_matrix_sync(af, &Ah[wm * 16 * 24], 24);
            wmma::load_matrix_sync(bf0, &Bh[(wn * 32) * 24], 24);
            wmma::load_matrix_sync(bf1, &Bh[(wn * 32 + 16) * 24], 24);
            wmma::mma_sync(c0, af, bf0, c0);
            wmma::mma_sync(c1, af, bf1, c1);
        }
        __syncthreads();
    }

    wmma::store_matrix_sync(&Cst[(wm * 16) * 72 + wn * 32], c0, 72, wmma::mem_row_major);
    wmma::store_matrix_sync(&Cst[(wm * 16) * 72 + wn * 32 + 16], c1, 72, wmma::mem_row_major);
    __syncthreads();

    const int tx = tid & 15;
    const int ty = tid >> 4;
#pragma unroll
    for (int i = 0; i < 4; i++) {
        int m = m0 + ty * 4 + i;
        float4 v = *(const float4*)&Cst[(ty * 4 + i) * 72 + tx * 4];
        *(float4*)&out[(size_t)m * DM + n0 + tx * 4] = v;
    }
}

// ---------------------------------------------------------------------------
// Fused scores(tanh, h16 chain) + softmax + AV (R10 best; phase 4 stores h16).
// ---------------------------------------------------------------------------
#define SCP 516
__global__ __launch_bounds__(256, 2) void attn_fused_kernel(const float* __restrict__ v_a,
                                                            float* __restrict__ attn) {
    extern __shared__ float sm[];
    float* sc = sm;              // 32 * 516
    float* Bs = sm + 32 * SCP;   // 32 * 68

    __shared__ unsigned int vas_h[32];

    const int bh = blockIdx.x;
    const int t0 = blockIdx.y * 32;
    const int h = bh & 3;
    const int tid = threadIdx.x;
    const int lane = tid & 31;
    const int w = tid >> 5;

    if (tid < 16) {
        float4 v = ((const float4*)(v_a + h * DH))[tid];
        __half2 h0 = __floats2half2_rn(v.x, v.y);
        __half2 h1 = __floats2half2_rn(v.z, v.w);
        vas_h[tid * 2] = *(unsigned int*)&h0;
        vas_h[tid * 2 + 1] = *(unsigned int*)&h1;
    }
    __syncthreads();

    // ---- Phase 1: scores -> sc (8 s-streams per warp, h16 chains) -------------
    {
        uint4 qreg[8];
        const uint4* qg = (const uint4*)(g_Qh + ((size_t)bh * TT + t0 + lane) * 32);
#pragma unroll
        for (int i = 0; i < 8; i++) qreg[i] = qg[i];

#pragma unroll 1
        for (int g = 0; g < 8; g++) {
            const int sl = w * 64 + g * 8;
            const uint4* K0 = (const uint4*)(g_Kh + ((size_t)bh * SS + sl) * 32);
            const uint4* K1 = K0 + 8;
            const uint4* K2 = K0 + 16;
            const uint4* K3 = K0 + 24;
            const uint4* K4 = K0 + 32;
            const uint4* K5 = K0 + 40;
            const uint4* K6 = K0 + 48;
            const uint4* K7 = K0 + 56;
            float a0 = 0.f, a1 = 0.f, a2 = 0.f, a3 = 0.f;
            float a4 = 0.f, a5 = 0.f, a6 = 0.f, a7 = 0.f;
#pragma unroll
            for (int i = 0; i < 8; i++) {
                uint4 vah = *(const uint4*)&vas_h[i * 4];
                uint4 q = qreg[i];
                a0 += dot8h(q, K0[i], vah);
                a1 += dot8h(q, K1[i], vah);
                a2 += dot8h(q, K2[i], vah);
                a3 += dot8h(q, K3[i], vah);
                a4 += dot8h(q, K4[i], vah);
                a5 += dot8h(q, K5[i], vah);
                a6 += dot8h(q, K6[i], vah);
                a7 += dot8h(q, K7[i], vah);
            }
            *(float4*)&sc[lane * SCP + sl] =
                make_float4(a0 * 0.125f, a1 * 0.125f, a2 * 0.125f, a3 * 0.125f);
            *(float4*)&sc[lane * SCP + sl + 4] =
                make_float4(a4 * 0.125f, a5 * 0.125f, a6 * 0.125f, a7 * 0.125f);
        }
    }
    __syncthreads();

    // ---- Phase 2: softmax -------------------------------------------------------
#pragma unroll 1
    for (int q = 0; q < 4; q++) {
        int r = w * 4 + q;
        float4* row = (float4*)&sc[r * SCP];
        float4 x0 = row[lane], x1 = row[lane + 32], x2 = row[lane + 64], x3 = row[lane + 96];
        float m = fmaxf(fmaxf(fmaxf(x0.x, x0.y), fmaxf(x0.z, x0.w)),
                        fmaxf(fmaxf(x1.x, x1.y), fmaxf(x1.z, x1.w)));
        m = fmaxf(m, fmaxf(fmaxf(fmaxf(x2.x, x2.y), fmaxf(x2.z, x2.w)),
                           fmaxf(fmaxf(x3.x, x3.y), fmaxf(x3.z, x3.w))));
#pragma unroll
        for (int o = 16; o; o >>= 1) m = fmaxf(m, __shfl_xor_sync(0xffffffffu, m, o));
        x0.x = __expf(x0.x - m); x0.y = __expf(x0.y - m); x0.z = __expf(x0.z - m); x0.w = __expf(x0.w - m);
        x1.x = __expf(x1.x - m); x1.y = __expf(x1.y - m); x1.z = __expf(x1.z - m); x1.w = __expf(x1.w - m);
        x2.x = __expf(x2.x - m); x2.y = __expf(x2.y - m); x2.z = __expf(x2.z - m); x2.w = __expf(x2.w - m);
        x3.x = __expf(x3.x - m); x3.y = __expf(x3.y - m); x3.z = __expf(x3.z - m); x3.w = __expf(x3.w - m);
        float s = (x0.x + x0.y + x0.z + x0.w) + (x1.x + x1.y + x1.z + x1.w)
                + (x2.x + x2.y + x2.z + x2.w) + (x3.x + x3.y + x3.z + x3.w);
#pragma unroll
        for (int o = 16; o; o >>= 1) s += __shfl_xor_sync(0xffffffffu, s, o);
        float inv = 1.0f / s;
        x0.x *= inv; x0.y *= inv; x0.z *= inv; x0.w *= inv;
        x1.x *= inv; x1.y *= inv; x1.z *= inv; x1.w *= inv;
        x2.x *= inv; x2.y *= inv; x2.z *= inv; x2.w *= inv;
        x3.x *= inv; x3.y *= inv; x3.z *= inv; x3.w *= inv;
        row[lane] = x0; row[lane + 32] = x1; row[lane + 64] = x2; row[lane + 96] = x3;
    }
    __syncthreads();

    // ---- Phase 3: write attn -----------------------------------------------------
    {
        float* arow = attn + ((size_t)bh * TT + t0) * SS;
        for (int i = tid; i < 32 * 128; i += 256) {
            int r = i >> 7, c = i & 127;
            *(float4*)&arow[(size_t)r * SS + c * 4] = *(const float4*)&sc[r * SCP + c * 4];
        }
    }

    // ---- Phase 4: AV ---------------------------------------------------------------
    const float* Vg = g_V + (size_t)bh * SS * DH;
    const int tx = tid & 15;
    const int tyy = tid >> 4;
    unsigned long long acc[2][2];
    acc[0][0] = acc[0][1] = acc[1][0] = acc[1][1] = 0ull;

#pragma unroll 1
    for (int s0 = 0; s0 < SS; s0 += 32) {
        __syncthreads();
        for (int i = tid; i < 512; i += 256) {
            int rr = i >> 4, cc = i & 15;
            *(float4*)&Bs[rr * 68 + cc * 4] = *(const float4*)&Vg[(size_t)(s0 + rr) * DH + cc * 4];
        }
        __syncthreads();
#pragma unroll 8
        for (int kk = 0; kk < 32; kk++) {
            ulonglong2 b2 = *(const ulonglong2*)&Bs[kk * 68 + tx * 4];
            float a0 = sc[(size_t)(tyy * 2) * SCP + s0 + kk];
            float a1 = sc[(size_t)(tyy * 2 + 1) * SCP + s0 + kk];
            unsigned long long aa;
            aa = pack2(a0, a0); acc[0][0] = fma2(aa, b2.x, acc[0][0]); acc[0][1] = fma2(aa, b2.y, acc[0][1]);
            aa = pack2(a1, a1); acc[1][0] = fma2(aa, b2.x, acc[1][0]); acc[1][1] = fma2(aa, b2.y, acc[1][1]);
        }
    }

    {
        const int b = bh >> 2;
#pragma unroll
        for (int i = 0; i < 2; i++) {
            int t = t0 + tyy * 2 + i;
            float2 c01 = unpack2(acc[i][0]);
            float2 c23 = unpack2(acc[i][1]);
            __half2 h0 = __floats2half2_rn(c01.x, c01.y);
            __half2 h1 = __floats2half2_rn(c23.x, c23.y);
            uint2 u = make_uint2(*(unsigned int*)&h0, *(unsigned int*)&h1);
            *(uint2*)&g_attH[((size_t)(b * TT + t)) * DM + h * DH + tx * 4] = u;
        }
    }
}

// ---------------------------------------------------------------------------
extern "C" void kernel_launch(void* const* d_in, const int* in_sizes, int n_in,
                              void* d_out, int out_size) {
    const float* query = (const float*)d_in[0];
    const float* key   = (const float*)d_in[1];
    const float* value = (const float*)d_in[2];
    const float* w_q   = (const float*)d_in[3];
    const float* w_k   = (const float*)d_in[4];
    const float* w_v   = (const float*)d_in[5];
    const float* v_a   = (const float*)d_in[6];
    const float* w_o   = (const float*)d_in[7];

    float* out  = (float*)d_out;
    float* attn = out + (size_t)BB * TT * DM;

    // Q/K/V projections (tensor cores)
    hgemm_proj<<<dim3(32, 4, 3), 256>>>(query, key, value, w_q, w_k, w_v);

    // fused additive-attention (scores + softmax + AV)
    const int dyn = (32 * SCP + 32 * 68) * sizeof(float);   // ~74.8 KB
    cudaFuncSetAttribute(attn_fused_kernel,
                         cudaFuncAttributeMaxDynamicSharedMemorySize, dyn);
    attn_fused_kernel<<<dim3(BHN, TT / 32), 256, dyn>>>(v_a, attn);

    // output projection (tensor cores)
    hgemm_out<<<dim3(32, 4), 256>>>(w_o, out);
}

// round 13
// speedup vs baseline: 1.2350x; 1.0308x over previous
#include <cuda_runtime.h>
#include <cuda_fp16.h>
#include <mma.h>
using namespace nvcuda;

#define DM 256
#define NH 4
#define DH 64
#define BB 4
#define TT 512
#define SS 512
#define BHN 16

// Scratch (no allocs -> device globals)
__device__ unsigned int g_Qh[BHN * TT * 32];  // half2 [bh][t][d/2]
__device__ unsigned int g_Kh[BHN * SS * 32];  // half2 [bh][s][d/2]
__device__ float g_V[BHN * SS * DH];          // f32   [bh][s][d]
__device__ __half g_attH[BB * TT * DM];       // attended, fp16 [b][t][h*64+d]

// ---- packed helpers -------------------------------------------------------
__device__ __forceinline__ unsigned long long pack2(float x, float y) {
    unsigned long long r;
    asm("mov.b64 %0, {%1, %2};" : "=l"(r) : "f"(x), "f"(y));
    return r;
}
__device__ __forceinline__ float2 unpack2(unsigned long long v) {
    float2 r;
    asm("mov.b64 {%0, %1}, %2;" : "=f"(r.x), "=f"(r.y) : "l"(v));
    return r;
}
__device__ __forceinline__ unsigned long long fma2(unsigned long long a,
                                                   unsigned long long b,
                                                   unsigned long long c) {
    unsigned long long d;
    asm("fma.rn.f32x2 %0, %1, %2, %3;" : "=l"(d) : "l"(a), "l"(b), "l"(c));
    return d;
}
__device__ __forceinline__ unsigned int htanh2(unsigned int x) {
    unsigned int y;
    asm("tanh.approx.f16x2 %0, %1;" : "=r"(y) : "r"(x));
    return y;
}
__device__ __forceinline__ unsigned int hadd2u(unsigned int a, unsigned int b) {
    unsigned int y;
    asm("add.rn.f16x2 %0, %1, %2;" : "=r"(y) : "r"(a), "r"(b));
    return y;
}
__device__ __forceinline__ unsigned int hmul2u(unsigned int a, unsigned int b) {
    unsigned int y;
    asm("mul.rn.f16x2 %0, %1, %2;" : "=r"(y) : "r"(a), "r"(b));
    return y;
}
__device__ __forceinline__ unsigned int hfma2u(unsigned int a, unsigned int b, unsigned int c) {
    unsigned int y;
    asm("fma.rn.f16x2 %0, %1, %2, %3;" : "=r"(y) : "r"(a), "r"(b), "r"(c));
    return y;
}
__device__ __forceinline__ float2 h2f2(unsigned int h) {
    __half2 v = *reinterpret_cast<__half2*>(&h);
    return __half22float2(v);
}

// 8-element weighted tanh dot, fp16 product chain (len 4), fp32 result.
__device__ __forceinline__ float dot8h(uint4 q, uint4 k, uint4 vah) {
    unsigned int t0 = htanh2(hadd2u(q.x, k.x));
    unsigned int t1 = htanh2(hadd2u(q.y, k.y));
    unsigned int t2 = htanh2(hadd2u(q.z, k.z));
    unsigned int t3 = htanh2(hadd2u(q.w, k.w));
    unsigned int c = hmul2u(vah.x, t0);
    c = hfma2u(vah.y, t1, c);
    c = hfma2u(vah.z, t2, c);
    c = hfma2u(vah.w, t3, c);
    float2 f = h2f2(c);
    return f.x + f.y;
}

// ---------------------------------------------------------------------------
// Tensor-core projection GEMM v2: 64x64 tile, k-chunk 32, double-buffered.
// 256 thr = 8 warps (4m x 2n). z = 0/1/2 -> g_Qh (h16), g_Kh (h16), g_V (f32).
// ---------------------------------------------------------------------------
#define KP 40   // smem pitch in halves for 32-k chunk
__global__ __launch_bounds__(256) void hgemm_proj(const float* __restrict__ q_in,
                                                  const float* __restrict__ k_in,
                                                  const float* __restrict__ v_in,
                                                  const float* __restrict__ w_q,
                                                  const float* __restrict__ w_k,
                                                  const float* __restrict__ w_v) {
    __shared__ __align__(32) __half Ah[2][64 * KP];
    __shared__ __align__(32) __half Bh[2][64 * KP];
    __shared__ __align__(16) float Cst[64 * 72];

    const int mode = blockIdx.z;
    const float* A = (mode == 0) ? q_in : (mode == 1) ? k_in : v_in;
    const float* W = (mode == 0) ? w_q : (mode == 1) ? w_k : w_v;

    const int m0 = blockIdx.x * 64;
    const int n0 = blockIdx.y * 64;
    const int tid = threadIdx.x;
    const int w = tid >> 5;
    const int wm = w >> 1;        // 0..3
    const int wn = w & 1;         // 0..1
    const int r = tid >> 2;       // 0..63
    const int c8 = (tid & 3) * 8; // 0,8,16,24

    wmma::fragment<wmma::accumulator, 16, 16, 16, float> c0, c1;
    wmma::fill_fragment(c0, 0.0f);
    wmma::fill_fragment(c1, 0.0f);

    const float* Aptr = A + (size_t)(m0 + r) * DM + c8;
    const float* Wptr = W + (size_t)(n0 + r) * DM + c8;

    float4 ra0 = *(const float4*)Aptr;
    float4 ra1 = *(const float4*)(Aptr + 4);
    float4 rw0 = *(const float4*)Wptr;
    float4 rw1 = *(const float4*)(Wptr + 4);

#pragma unroll 1
    for (int kc = 0; kc < 8; kc++) {
        const int p = kc & 1;
        {
            __half2 a0 = __floats2half2_rn(ra0.x, ra0.y), a1 = __floats2half2_rn(ra0.z, ra0.w);
            __half2 a2 = __floats2half2_rn(ra1.x, ra1.y), a3 = __floats2half2_rn(ra1.z, ra1.w);
            __half2 b0 = __floats2half2_rn(rw0.x, rw0.y), b1 = __floats2half2_rn(rw0.z, rw0.w);
            __half2 b2 = __floats2half2_rn(rw1.x, rw1.y), b3 = __floats2half2_rn(rw1.z, rw1.w);
            *(__half2*)&Ah[p][r * KP + c8] = a0;
            *(__half2*)&Ah[p][r * KP + c8 + 2] = a1;
            *(__half2*)&Ah[p][r * KP + c8 + 4] = a2;
            *(__half2*)&Ah[p][r * KP + c8 + 6] = a3;
            *(__half2*)&Bh[p][r * KP + c8] = b0;
            *(__half2*)&Bh[p][r * KP + c8 + 2] = b1;
            *(__half2*)&Bh[p][r * KP + c8 + 4] = b2;
            *(__half2*)&Bh[p][r * KP + c8 + 6] = b3;
        }
        __syncthreads();
        if (kc < 7) {
            ra0 = *(const float4*)(Aptr + (kc + 1) * 32);
            ra1 = *(const float4*)(Aptr + (kc + 1) * 32 + 4);
            rw0 = *(const float4*)(Wptr + (kc + 1) * 32);
            rw1 = *(const float4*)(Wptr + (kc + 1) * 32 + 4);
        }
#pragma unroll
        for (int kf = 0; kf < 2; kf++) {
            wmma::fragment<wmma::matrix_a, 16, 16, 16, __half, wmma::row_major> af;
            wmma::fragment<wmma::matrix_b, 16, 16, 16, __half, wmma::col_major> bf0, bf1;
            wmma::load_matrix_sync(af, &Ah[p][wm * 16 * KP + kf * 16], KP);
            wmma::load_matrix_sync(bf0, &Bh[p][(wn * 32) * KP + kf * 16], KP);
            wmma::load_matrix_sync(bf1, &Bh[p][(wn * 32 + 16) * KP + kf * 16], KP);
            wmma::mma_sync(c0, af, bf0, c0);
            wmma::mma_sync(c1, af, bf1, c1);
        }
        __syncthreads();
    }

    wmma::store_matrix_sync(&Cst[(wm * 16) * 72 + wn * 32], c0, 72, wmma::mem_row_major);
    wmma::store_matrix_sync(&Cst[(wm * 16) * 72 + wn * 32 + 16], c1, 72, wmma::mem_row_major);
    __syncthreads();

    const int tx = tid & 15;
    const int ty = tid >> 4;
    const int hh = n0 >> 6;
#pragma unroll
    for (int i = 0; i < 4; i++) {
        int m = m0 + ty * 4 + i;
        int bb = m >> 9, t = m & 511;
        float4 v = *(const float4*)&Cst[(ty * 4 + i) * 72 + tx * 4];
        if (mode <= 1) {
            unsigned int* dst = (mode == 0) ? g_Qh : g_Kh;
            __half2 h0 = __floats2half2_rn(v.x, v.y);
            __half2 h1 = __floats2half2_rn(v.z, v.w);
            uint2 u = make_uint2(*(unsigned int*)&h0, *(unsigned int*)&h1);
            *(uint2*)&dst[((size_t)(bb * NH + hh) * TT + t) * 32 + tx * 2] = u;
        } else {
            *(float4*)&g_V[((size_t)(bb * NH + hh) * TT + t) * DH + tx * 4] = v;
        }
    }
}

// ---------------------------------------------------------------------------
// Tensor-core output GEMM v2: out = g_attH (fp16) @ w_o.T, k-chunk 32,
// double-buffered.
// ---------------------------------------------------------------------------
__global__ __launch_bounds__(256) void hgemm_out(const float* __restrict__ w_o,
                                                 float* __restrict__ out) {
    __shared__ __align__(32) __half Ah[2][64 * KP];
    __shared__ __align__(32) __half Bh[2][64 * KP];
    __shared__ __align__(16) float Cst[64 * 72];

    const int m0 = blockIdx.x * 64;
    const int n0 = blockIdx.y * 64;
    const int tid = threadIdx.x;
    const int w = tid >> 5;
    const int wm = w >> 1;
    const int wn = w & 1;
    const int r = tid >> 2;
    const int c8 = (tid & 3) * 8;

    wmma::fragment<wmma::accumulator, 16, 16, 16, float> c0, c1;
    wmma::fill_fragment(c0, 0.0f);
    wmma::fill_fragment(c1, 0.0f);

    const __half* Aptr = g_attH + (size_t)(m0 + r) * DM + c8;
    const float* Wptr = w_o + (size_t)(n0 + r) * DM + c8;

    uint4 ra = *(const uint4*)Aptr;
    float4 rw0 = *(const float4*)Wptr;
    float4 rw1 = *(const float4*)(Wptr + 4);

#pragma unroll 1
    for (int kc = 0; kc < 8; kc++) {
        const int p = kc & 1;
        {
            __half2 b0 = __floats2half2_rn(rw0.x, rw0.y), b1 = __floats2half2_rn(rw0.z, rw0.w);
            __half2 b2 = __floats2half2_rn(rw1.x, rw1.y), b3 = __floats2half2_rn(rw1.z, rw1.w);
            *(uint4*)&Ah[p][r * KP + c8] = ra;
            *(__half2*)&Bh[p][r * KP + c8] = b0;
            *(__half2*)&Bh[p][r * KP + c8 + 2] = b1;
            *(__half2*)&Bh[p][r * KP + c8 + 4] = b2;
            *(__half2*)&Bh[p][r * KP + c8 + 6] = b3;
        }
        __syncthreads();
        if (kc < 7) {
            ra = *(const uint4*)(Aptr + (kc + 1) * 32);
            rw0 = *(const float4*)(Wptr + (kc + 1) * 32);
            rw1 = *(const float4*)(Wptr + (kc + 1) * 32 + 4);
        }
#pragma unroll
        for (int kf = 0; kf < 2; kf++) {
            wmma::fragment<wmma::matrix_a, 16, 16, 16, __half, wmma::row_major> af;
            wmma::fragment<wmma::matrix_b, 16, 16, 16, __half, wmma::col_major> bf0, bf1;
            wmma::load_matrix_sync(af, &Ah[p][wm * 16 * KP + kf * 16], KP);
            wmma::load_matrix_sync(bf0, &Bh[p][(wn * 32) * KP + kf * 16], KP);
            wmma::load_matrix_sync(bf1, &Bh[p][(wn * 32 + 16) * KP + kf * 16], KP);
            wmma::mma_sync(c0, af, bf0, c0);
            wmma::mma_sync(c1, af, bf1, c1);
        }
        __syncthreads();
    }

    wmma::store_matrix_sync(&Cst[(wm * 16) * 72 + wn * 32], c0, 72, wmma::mem_row_major);
    wmma::store_matrix_sync(&Cst[(wm * 16) * 72 + wn * 32 + 16], c1, 72, wmma::mem_row_major);
    __syncthreads();

    const int tx = tid & 15;
    const int ty = tid >> 4;
#pragma unroll
    for (int i = 0; i < 4; i++) {
        int m = m0 + ty * 4 + i;
        float4 v = *(const float4*)&Cst[(ty * 4 + i) * 72 + tx * 4];
        *(float4*)&out[(size_t)m * DM + n0 + tx * 4] = v;
    }
}

// ---------------------------------------------------------------------------
// Fused scores(tanh, h16 chain) + softmax(+attn write) + AV.
// Phase 3 folded into phase 2: normalized rows written to global directly
// from registers (coalesced), saving a full smem re-read pass.
// ---------------------------------------------------------------------------
#define SCP 516
__global__ __launch_bounds__(256, 2) void attn_fused_kernel(const float* __restrict__ v_a,
                                                            float* __restrict__ attn) {
    extern __shared__ float sm[];
    float* sc = sm;              // 32 * 516
    float* Bs = sm + 32 * SCP;   // 32 * 68

    __shared__ unsigned int vas_h[32];

    const int bh = blockIdx.x;
    const int t0 = blockIdx.y * 32;
    const int h = bh & 3;
    const int tid = threadIdx.x;
    const int lane = tid & 31;
    const int w = tid >> 5;

    if (tid < 16) {
        float4 v = ((const float4*)(v_a + h * DH))[tid];
        __half2 h0 = __floats2half2_rn(v.x, v.y);
        __half2 h1 = __floats2half2_rn(v.z, v.w);
        vas_h[tid * 2] = *(unsigned int*)&h0;
        vas_h[tid * 2 + 1] = *(unsigned int*)&h1;
    }
    __syncthreads();

    // ---- Phase 1: scores -> sc (8 s-streams per warp, h16 chains) -------------
    {
        uint4 qreg[8];
        const uint4* qg = (const uint4*)(g_Qh + ((size_t)bh * TT + t0 + lane) * 32);
#pragma unroll
        for (int i = 0; i < 8; i++) qreg[i] = qg[i];

#pragma unroll 1
        for (int g = 0; g < 8; g++) {
            const int sl = w * 64 + g * 8;
            const uint4* K0 = (const uint4*)(g_Kh + ((size_t)bh * SS + sl) * 32);
            const uint4* K1 = K0 + 8;
            const uint4* K2 = K0 + 16;
            const uint4* K3 = K0 + 24;
            const uint4* K4 = K0 + 32;
            const uint4* K5 = K0 + 40;
            const uint4* K6 = K0 + 48;
            const uint4* K7 = K0 + 56;
            float a0 = 0.f, a1 = 0.f, a2 = 0.f, a3 = 0.f;
            float a4 = 0.f, a5 = 0.f, a6 = 0.f, a7 = 0.f;
#pragma unroll
            for (int i = 0; i < 8; i++) {
                uint4 vah = *(const uint4*)&vas_h[i * 4];
                uint4 q = qreg[i];
                a0 += dot8h(q, K0[i], vah);
                a1 += dot8h(q, K1[i], vah);
                a2 += dot8h(q, K2[i], vah);
                a3 += dot8h(q, K3[i], vah);
                a4 += dot8h(q, K4[i], vah);
                a5 += dot8h(q, K5[i], vah);
                a6 += dot8h(q, K6[i], vah);
                a7 += dot8h(q, K7[i], vah);
            }
            *(float4*)&sc[lane * SCP + sl] =
                make_float4(a0 * 0.125f, a1 * 0.125f, a2 * 0.125f, a3 * 0.125f);
            *(float4*)&sc[lane * SCP + sl + 4] =
                make_float4(a4 * 0.125f, a5 * 0.125f, a6 * 0.125f, a7 * 0.125f);
        }
    }
    __syncthreads();

    // ---- Phase 2: softmax + direct attn writeback ------------------------------
#pragma unroll 1
    for (int q = 0; q < 4; q++) {
        int r = w * 4 + q;
        float4* row = (float4*)&sc[r * SCP];
        float4 x0 = row[lane], x1 = row[lane + 32], x2 = row[lane + 64], x3 = row[lane + 96];
        float m = fmaxf(fmaxf(fmaxf(x0.x, x0.y), fmaxf(x0.z, x0.w)),
                        fmaxf(fmaxf(x1.x, x1.y), fmaxf(x1.z, x1.w)));
        m = fmaxf(m, fmaxf(fmaxf(fmaxf(x2.x, x2.y), fmaxf(x2.z, x2.w)),
                           fmaxf(fmaxf(x3.x, x3.y), fmaxf(x3.z, x3.w))));
#pragma unroll
        for (int o = 16; o; o >>= 1) m = fmaxf(m, __shfl_xor_sync(0xffffffffu, m, o));
        x0.x = __expf(x0.x - m); x0.y = __expf(x0.y - m); x0.z = __expf(x0.z - m); x0.w = __expf(x0.w - m);
        x1.x = __expf(x1.x - m); x1.y = __expf(x1.y - m); x1.z = __expf(x1.z - m); x1.w = __expf(x1.w - m);
        x2.x = __expf(x2.x - m); x2.y = __expf(x2.y - m); x2.z = __expf(x2.z - m); x2.w = __expf(x2.w - m);
        x3.x = __expf(x3.x - m); x3.y = __expf(x3.y - m); x3.z = __expf(x3.z - m); x3.w = __expf(x3.w - m);
        float s = (x0.x + x0.y + x0.z + x0.w) + (x1.x + x1.y + x1.z + x1.w)
                + (x2.x + x2.y + x2.z + x2.w) + (x3.x + x3.y + x3.z + x3.w);
#pragma unroll
        for (int o = 16; o; o >>= 1) s += __shfl_xor_sync(0xffffffffu, s, o);
        float inv = 1.0f / s;
        x0.x *= inv; x0.y *= inv; x0.z *= inv; x0.w *= inv;
        x1.x *= inv; x1.y *= inv; x1.z *= inv; x1.w *= inv;
        x2.x *= inv; x2.y *= inv; x2.z *= inv; x2.w *= inv;
        x3.x *= inv; x3.y *= inv; x3.z *= inv; x3.w *= inv;
        row[lane] = x0; row[lane + 32] = x1; row[lane + 64] = x2; row[lane + 96] = x3;
        float4* gout = (float4*)(attn + ((size_t)bh * TT + t0 + r) * SS);
        gout[lane] = x0; gout[lane + 32] = x1; gout[lane + 64] = x2; gout[lane + 96] = x3;
    }
    __syncthreads();

    // ---- Phase 4: AV (32t x 64d, micro 2t x 4d) ---------------------------------
    const float* Vg = g_V + (size_t)bh * SS * DH;
    const int tx = tid & 15;
    const int tyy = tid >> 4;
    unsigned long long acc[2][2];
    acc[0][0] = acc[0][1] = acc[1][0] = acc[1][1] = 0ull;

#pragma unroll 1
    for (int s0 = 0; s0 < SS; s0 += 32) {
        __syncthreads();
        for (int i = tid; i < 512; i += 256) {
            int rr = i >> 4, cc = i & 15;
            *(float4*)&Bs[rr * 68 + cc * 4] = *(const float4*)&Vg[(size_t)(s0 + rr) * DH + cc * 4];
        }
        __syncthreads();
#pragma unroll 8
        for (int kk = 0; kk < 32; kk++) {
            ulonglong2 b2 = *(const ulonglong2*)&Bs[kk * 68 + tx * 4];
            float a0 = sc[(size_t)(tyy * 2) * SCP + s0 + kk];
            float a1 = sc[(size_t)(tyy * 2 + 1) * SCP + s0 + kk];
            unsigned long long aa;
            aa = pack2(a0, a0); acc[0][0] = fma2(aa, b2.x, acc[0][0]); acc[0][1] = fma2(aa, b2.y, acc[0][1]);
            aa = pack2(a1, a1); acc[1][0] = fma2(aa, b2.x, acc[1][0]); acc[1][1] = fma2(aa, b2.y, acc[1][1]);
        }
    }

    {
        const int b = bh >> 2;
#pragma unroll
        for (int i = 0; i < 2; i++) {
            int t = t0 + tyy * 2 + i;
            float2 c01 = unpack2(acc[i][0]);
            float2 c23 = unpack2(acc[i][1]);
            __half2 h0 = __floats2half2_rn(c01.x, c01.y);
            __half2 h1 = __floats2half2_rn(c23.x, c23.y);
            uint2 u = make_uint2(*(unsigned int*)&h0, *(unsigned int*)&h1);
            *(uint2*)&g_attH[((size_t)(b * TT + t)) * DM + h * DH + tx * 4] = u;
        }
    }
}

// ---------------------------------------------------------------------------
extern "C" void kernel_launch(void* const* d_in, const int* in_sizes, int n_in,
                              void* d_out, int out_size) {
    const float* query = (const float*)d_in[0];
    const float* key   = (const float*)d_in[1];
    const float* value = (const float*)d_in[2];
    const float* w_q   = (const float*)d_in[3];
    const float* w_k   = (const float*)d_in[4];
    const float* w_v   = (const float*)d_in[5];
    const float* v_a   = (const float*)d_in[6];
    const float* w_o   = (const float*)d_in[7];

    float* out  = (float*)d_out;
    float* attn = out + (size_t)BB * TT * DM;

    // Q/K/V projections (tensor cores, double-buffered)
    hgemm_proj<<<dim3(32, 4, 3), 256>>>(query, key, value, w_q, w_k, w_v);

    // fused additive-attention (scores + softmax/attn-write + AV)
    const int dyn = (32 * SCP + 32 * 68) * sizeof(float);   // ~74.8 KB
    cudaFuncSetAttribute(attn_fused_kernel,
                         cudaFuncAttributeMaxDynamicSharedMemorySize, dyn);
    attn_fused_kernel<<<dim3(BHN, TT / 32), 256, dyn>>>(v_a, attn);

    // output projection (tensor cores, double-buffered)
    hgemm_out<<<dim3(32, 4), 256>>>(w_o, out);
}

// round 14
// speedup vs baseline: 1.3849x; 1.1214x over previous
#include <cuda_runtime.h>
#include <cuda_fp16.h>
#include <mma.h>
using namespace nvcuda;

#define DM 256
#define NH 4
#define DH 64
#define BB 4
#define TT 512
#define SS 512
#define BHN 16

// Scratch (no allocs -> device globals)
__device__ unsigned int g_Qh[BHN * TT * 32];  // half2 [bh][t][d/2]
__device__ unsigned int g_Kh[BHN * SS * 32];  // half2 [bh][s][d/2]
__device__ __half g_Vh[BHN * SS * DH];        // fp16  [bh][s][d]
__device__ __half g_attH[BB * TT * DM];       // attended, fp16 [b][t][h*64+d]

// ---- packed helpers -------------------------------------------------------
__device__ __forceinline__ unsigned int htanh2(unsigned int x) {
    unsigned int y;
    asm("tanh.approx.f16x2 %0, %1;" : "=r"(y) : "r"(x));
    return y;
}
__device__ __forceinline__ unsigned int hadd2u(unsigned int a, unsigned int b) {
    unsigned int y;
    asm("add.rn.f16x2 %0, %1, %2;" : "=r"(y) : "r"(a), "r"(b));
    return y;
}
__device__ __forceinline__ unsigned int hmul2u(unsigned int a, unsigned int b) {
    unsigned int y;
    asm("mul.rn.f16x2 %0, %1, %2;" : "=r"(y) : "r"(a), "r"(b));
    return y;
}
__device__ __forceinline__ unsigned int hfma2u(unsigned int a, unsigned int b, unsigned int c) {
    unsigned int y;
    asm("fma.rn.f16x2 %0, %1, %2, %3;" : "=r"(y) : "r"(a), "r"(b), "r"(c));
    return y;
}
__device__ __forceinline__ float2 h2f2(unsigned int h) {
    __half2 v = *reinterpret_cast<__half2*>(&h);
    return __half22float2(v);
}

// 8-element weighted tanh dot, fp16 product chain (len 4), fp32 result.
__device__ __forceinline__ float dot8h(uint4 q, uint4 k, uint4 vah) {
    unsigned int t0 = htanh2(hadd2u(q.x, k.x));
    unsigned int t1 = htanh2(hadd2u(q.y, k.y));
    unsigned int t2 = htanh2(hadd2u(q.z, k.z));
    unsigned int t3 = htanh2(hadd2u(q.w, k.w));
    unsigned int c = hmul2u(vah.x, t0);
    c = hfma2u(vah.y, t1, c);
    c = hfma2u(vah.z, t2, c);
    c = hfma2u(vah.w, t3, c);
    float2 f = h2f2(c);
    return f.x + f.y;
}

// ---------------------------------------------------------------------------
// Tensor-core projection GEMM: 64x64 tile, k-chunk 32, double-buffered.
// 256 thr = 8 warps (4m x 2n). z = 0/1/2 -> g_Qh (h16), g_Kh (h16), g_Vh (h16).
// ---------------------------------------------------------------------------
#define KP 40
__global__ __launch_bounds__(256) void hgemm_proj(const float* __restrict__ q_in,
                                                  const float* __restrict__ k_in,
                                                  const float* __restrict__ v_in,
                                                  const float* __restrict__ w_q,
                                                  const float* __restrict__ w_k,
                                                  const float* __restrict__ w_v) {
    __shared__ __align__(32) __half Ah[2][64 * KP];
    __shared__ __align__(32) __half Bh[2][64 * KP];
    __shared__ __align__(16) float Cst[64 * 72];

    const int mode = blockIdx.z;
    const float* A = (mode == 0) ? q_in : (mode == 1) ? k_in : v_in;
    const float* W = (mode == 0) ? w_q : (mode == 1) ? w_k : w_v;

    const int m0 = blockIdx.x * 64;
    const int n0 = blockIdx.y * 64;
    const int tid = threadIdx.x;
    const int w = tid >> 5;
    const int wm = w >> 1;
    const int wn = w & 1;
    const int r = tid >> 2;
    const int c8 = (tid & 3) * 8;

    wmma::fragment<wmma::accumulator, 16, 16, 16, float> c0, c1;
    wmma::fill_fragment(c0, 0.0f);
    wmma::fill_fragment(c1, 0.0f);

    const float* Aptr = A + (size_t)(m0 + r) * DM + c8;
    const float* Wptr = W + (size_t)(n0 + r) * DM + c8;

    float4 ra0 = *(const float4*)Aptr;
    float4 ra1 = *(const float4*)(Aptr + 4);
    float4 rw0 = *(const float4*)Wptr;
    float4 rw1 = *(const float4*)(Wptr + 4);

#pragma unroll 1
    for (int kc = 0; kc < 8; kc++) {
        const int p = kc & 1;
        {
            __half2 a0 = __floats2half2_rn(ra0.x, ra0.y), a1 = __floats2half2_rn(ra0.z, ra0.w);
            __half2 a2 = __floats2half2_rn(ra1.x, ra1.y), a3 = __floats2half2_rn(ra1.z, ra1.w);
            __half2 b0 = __floats2half2_rn(rw0.x, rw0.y), b1 = __floats2half2_rn(rw0.z, rw0.w);
            __half2 b2 = __floats2half2_rn(rw1.x, rw1.y), b3 = __floats2half2_rn(rw1.z, rw1.w);
            *(__half2*)&Ah[p][r * KP + c8] = a0;
            *(__half2*)&Ah[p][r * KP + c8 + 2] = a1;
            *(__half2*)&Ah[p][r * KP + c8 + 4] = a2;
            *(__half2*)&Ah[p][r * KP + c8 + 6] = a3;
            *(__half2*)&Bh[p][r * KP + c8] = b0;
            *(__half2*)&Bh[p][r * KP + c8 + 2] = b1;
            *(__half2*)&Bh[p][r * KP + c8 + 4] = b2;
            *(__half2*)&Bh[p][r * KP + c8 + 6] = b3;
        }
        __syncthreads();
        if (kc < 7) {
            ra0 = *(const float4*)(Aptr + (kc + 1) * 32);
            ra1 = *(const float4*)(Aptr + (kc + 1) * 32 + 4);
            rw0 = *(const float4*)(Wptr + (kc + 1) * 32);
            rw1 = *(const float4*)(Wptr + (kc + 1) * 32 + 4);
        }
#pragma unroll
        for (int kf = 0; kf < 2; kf++) {
            wmma::fragment<wmma::matrix_a, 16, 16, 16, __half, wmma::row_major> af;
            wmma::fragment<wmma::matrix_b, 16, 16, 16, __half, wmma::col_major> bf0, bf1;
            wmma::load_matrix_sync(af, &Ah[p][wm * 16 * KP + kf * 16], KP);
            wmma::load_matrix_sync(bf0, &Bh[p][(wn * 32) * KP + kf * 16], KP);
            wmma::load_matrix_sync(bf1, &Bh[p][(wn * 32 + 16) * KP + kf * 16], KP);
            wmma::mma_sync(c0, af, bf0, c0);
            wmma::mma_sync(c1, af, bf1, c1);
        }
        __syncthreads();
    }

    wmma::store_matrix_sync(&Cst[(wm * 16) * 72 + wn * 32], c0, 72, wmma::mem_row_major);
    wmma::store_matrix_sync(&Cst[(wm * 16) * 72 + wn * 32 + 16], c1, 72, wmma::mem_row_major);
    __syncthreads();

    const int tx = tid & 15;
    const int ty = tid >> 4;
    const int hh = n0 >> 6;
#pragma unroll
    for (int i = 0; i < 4; i++) {
        int m = m0 + ty * 4 + i;
        int bb = m >> 9, t = m & 511;
        float4 v = *(const float4*)&Cst[(ty * 4 + i) * 72 + tx * 4];
        __half2 h0 = __floats2half2_rn(v.x, v.y);
        __half2 h1 = __floats2half2_rn(v.z, v.w);
        uint2 u = make_uint2(*(unsigned int*)&h0, *(unsigned int*)&h1);
        if (mode <= 1) {
            unsigned int* dst = (mode == 0) ? g_Qh : g_Kh;
            *(uint2*)&dst[((size_t)(bb * NH + hh) * TT + t) * 32 + tx * 2] = u;
        } else {
            *(uint2*)&g_Vh[((size_t)(bb * NH + hh) * TT + t) * DH + tx * 4] = u;
        }
    }
}

// ---------------------------------------------------------------------------
// Tensor-core output GEMM: out = g_attH (fp16) @ w_o.T, k-chunk 32, dbuf.
// ---------------------------------------------------------------------------
__global__ __launch_bounds__(256) void hgemm_out(const float* __restrict__ w_o,
                                                 float* __restrict__ out) {
    __shared__ __align__(32) __half Ah[2][64 * KP];
    __shared__ __align__(32) __half Bh[2][64 * KP];
    __shared__ __align__(16) float Cst[64 * 72];

    const int m0 = blockIdx.x * 64;
    const int n0 = blockIdx.y * 64;
    const int tid = threadIdx.x;
    const int w = tid >> 5;
    const int wm = w >> 1;
    const int wn = w & 1;
    const int r = tid >> 2;
    const int c8 = (tid & 3) * 8;

    wmma::fragment<wmma::accumulator, 16, 16, 16, float> c0, c1;
    wmma::fill_fragment(c0, 0.0f);
    wmma::fill_fragment(c1, 0.0f);

    const __half* Aptr = g_attH + (size_t)(m0 + r) * DM + c8;
    const float* Wptr = w_o + (size_t)(n0 + r) * DM + c8;

    uint4 ra = *(const uint4*)Aptr;
    float4 rw0 = *(const float4*)Wptr;
    float4 rw1 = *(const float4*)(Wptr + 4);

#pragma unroll 1
    for (int kc = 0; kc < 8; kc++) {
        const int p = kc & 1;
        {
            __half2 b0 = __floats2half2_rn(rw0.x, rw0.y), b1 = __floats2half2_rn(rw0.z, rw0.w);
            __half2 b2 = __floats2half2_rn(rw1.x, rw1.y), b3 = __floats2half2_rn(rw1.z, rw1.w);
            *(uint4*)&Ah[p][r * KP + c8] = ra;
            *(__half2*)&Bh[p][r * KP + c8] = b0;
            *(__half2*)&Bh[p][r * KP + c8 + 2] = b1;
            *(__half2*)&Bh[p][r * KP + c8 + 4] = b2;
            *(__half2*)&Bh[p][r * KP + c8 + 6] = b3;
        }
        __syncthreads();
        if (kc < 7) {
            ra = *(const uint4*)(Aptr + (kc + 1) * 32);
            rw0 = *(const float4*)(Wptr + (kc + 1) * 32);
            rw1 = *(const float4*)(Wptr + (kc + 1) * 32 + 4);
        }
#pragma unroll
        for (int kf = 0; kf < 2; kf++) {
            wmma::fragment<wmma::matrix_a, 16, 16, 16, __half, wmma::row_major> af;
            wmma::fragment<wmma::matrix_b, 16, 16, 16, __half, wmma::col_major> bf0, bf1;
            wmma::load_matrix_sync(af, &Ah[p][wm * 16 * KP + kf * 16], KP);
            wmma::load_matrix_sync(bf0, &Bh[p][(wn * 32) * KP + kf * 16], KP);
            wmma::load_matrix_sync(bf1, &Bh[p][(wn * 32 + 16) * KP + kf * 16], KP);
            wmma::mma_sync(c0, af, bf0, c0);
            wmma::mma_sync(c1, af, bf1, c1);
        }
        __syncthreads();
    }

    wmma::store_matrix_sync(&Cst[(wm * 16) * 72 + wn * 32], c0, 72, wmma::mem_row_major);
    wmma::store_matrix_sync(&Cst[(wm * 16) * 72 + wn * 32 + 16], c1, 72, wmma::mem_row_major);
    __syncthreads();

    const int tx = tid & 15;
    const int ty = tid >> 4;
#pragma unroll
    for (int i = 0; i < 4; i++) {
        int m = m0 + ty * 4 + i;
        float4 v = *(const float4*)&Cst[(ty * 4 + i) * 72 + tx * 4];
        *(float4*)&out[(size_t)m * DM + n0 + tx * 4] = v;
    }
}

// ---------------------------------------------------------------------------
// Fused scores(tanh h16) + softmax(attn write + fp16 probs) + wmma AV.
// Block = (bh, 32 t rows). smem: sc f32 (scores / later wmma-C), pH fp16 probs.
// ---------------------------------------------------------------------------
#define SCP 516
#define PHP 520
__global__ __launch_bounds__(256, 2) void attn_fused_kernel(const float* __restrict__ v_a,
                                                            float* __restrict__ attn) {
    extern __shared__ float sm[];
    float* sc = sm;                                  // 32 * 516 f32
    __half* pH = (__half*)(sm + 32 * SCP);           // 32 * 520 fp16

    __shared__ unsigned int vas_h[32];

    const int bh = blockIdx.x;
    const int t0 = blockIdx.y * 32;
    const int h = bh & 3;
    const int tid = threadIdx.x;
    const int lane = tid & 31;
    const int w = tid >> 5;

    if (tid < 16) {
        float4 v = ((const float4*)(v_a + h * DH))[tid];
        __half2 h0 = __floats2half2_rn(v.x, v.y);
        __half2 h1 = __floats2half2_rn(v.z, v.w);
        vas_h[tid * 2] = *(unsigned int*)&h0;
        vas_h[tid * 2 + 1] = *(unsigned int*)&h1;
    }
    __syncthreads();

    // ---- Phase 1: scores -> sc (8 s-streams per warp, h16 chains) -------------
    {
        uint4 qreg[8];
        const uint4* qg = (const uint4*)(g_Qh + ((size_t)bh * TT + t0 + lane) * 32);
#pragma unroll
        for (int i = 0; i < 8; i++) qreg[i] = qg[i];

#pragma unroll 1
        for (int g = 0; g < 8; g++) {
            const int sl = w * 64 + g * 8;
            const uint4* K0 = (const uint4*)(g_Kh + ((size_t)bh * SS + sl) * 32);
            const uint4* K1 = K0 + 8;
            const uint4* K2 = K0 + 16;
            const uint4* K3 = K0 + 24;
            const uint4* K4 = K0 + 32;
            const uint4* K5 = K0 + 40;
            const uint4* K6 = K0 + 48;
            const uint4* K7 = K0 + 56;
            float a0 = 0.f, a1 = 0.f, a2 = 0.f, a3 = 0.f;
            float a4 = 0.f, a5 = 0.f, a6 = 0.f, a7 = 0.f;
#pragma unroll
            for (int i = 0; i < 8; i++) {
                uint4 vah = *(const uint4*)&vas_h[i * 4];
                uint4 q = qreg[i];
                a0 += dot8h(q, K0[i], vah);
                a1 += dot8h(q, K1[i], vah);
                a2 += dot8h(q, K2[i], vah);
                a3 += dot8h(q, K3[i], vah);
                a4 += dot8h(q, K4[i], vah);
                a5 += dot8h(q, K5[i], vah);
                a6 += dot8h(q, K6[i], vah);
                a7 += dot8h(q, K7[i], vah);
            }
            *(float4*)&sc[lane * SCP + sl] =
                make_float4(a0 * 0.125f, a1 * 0.125f, a2 * 0.125f, a3 * 0.125f);
            *(float4*)&sc[lane * SCP + sl + 4] =
                make_float4(a4 * 0.125f, a5 * 0.125f, a6 * 0.125f, a7 * 0.125f);
        }
    }
    __syncthreads();

    // ---- Phase 2: softmax -> attn (global f32) + pH (smem fp16) ----------------
#pragma unroll 1
    for (int q = 0; q < 4; q++) {
        int r = w * 4 + q;
        float4* row = (float4*)&sc[r * SCP];
        float4 x0 = row[lane], x1 = row[lane + 32], x2 = row[lane + 64], x3 = row[lane + 96];
        float m = fmaxf(fmaxf(fmaxf(x0.x, x0.y), fmaxf(x0.z, x0.w)),
                        fmaxf(fmaxf(x1.x, x1.y), fmaxf(x1.z, x1.w)));
        m = fmaxf(m, fmaxf(fmaxf(fmaxf(x2.x, x2.y), fmaxf(x2.z, x2.w)),
                           fmaxf(fmaxf(x3.x, x3.y), fmaxf(x3.z, x3.w))));
#pragma unroll
        for (int o = 16; o; o >>= 1) m = fmaxf(m, __shfl_xor_sync(0xffffffffu, m, o));
        x0.x = __expf(x0.x - m); x0.y = __expf(x0.y - m); x0.z = __expf(x0.z - m); x0.w = __expf(x0.w - m);
        x1.x = __expf(x1.x - m); x1.y = __expf(x1.y - m); x1.z = __expf(x1.z - m); x1.w = __expf(x1.w - m);
        x2.x = __expf(x2.x - m); x2.y = __expf(x2.y - m); x2.z = __expf(x2.z - m); x2.w = __expf(x2.w - m);
        x3.x = __expf(x3.x - m); x3.y = __expf(x3.y - m); x3.z = __expf(x3.z - m); x3.w = __expf(x3.w - m);
        float s = (x0.x + x0.y + x0.z + x0.w) + (x1.x + x1.y + x1.z + x1.w)
                + (x2.x + x2.y + x2.z + x2.w) + (x3.x + x3.y + x3.z + x3.w);
#pragma unroll
        for (int o = 16; o; o >>= 1) s += __shfl_xor_sync(0xffffffffu, s, o);
        float inv = 1.0f / s;
        x0.x *= inv; x0.y *= inv; x0.z *= inv; x0.w *= inv;
        x1.x *= inv; x1.y *= inv; x1.z *= inv; x1.w *= inv;
        x2.x *= inv; x2.y *= inv; x2.z *= inv; x2.w *= inv;
        x3.x *= inv; x3.y *= inv; x3.z *= inv; x3.w *= inv;
        // global attn (f32, exact path for the checked attn output)
        float4* gout = (float4*)(attn + ((size_t)bh * TT + t0 + r) * SS);
        gout[lane] = x0; gout[lane + 32] = x1; gout[lane + 64] = x2; gout[lane + 96] = x3;
        // fp16 probs for wmma AV
        __half2 p0 = __floats2half2_rn(x0.x, x0.y), p1 = __floats2half2_rn(x0.z, x0.w);
        __half2 p2 = __floats2half2_rn(x1.x, x1.y), p3 = __floats2half2_rn(x1.z, x1.w);
        __half2 p4 = __floats2half2_rn(x2.x, x2.y), p5 = __floats2half2_rn(x2.z, x2.w);
        __half2 p6 = __floats2half2_rn(x3.x, x3.y), p7 = __floats2half2_rn(x3.z, x3.w);
        uint2* ph = (uint2*)&pH[r * PHP];
        ph[lane] = make_uint2(*(unsigned int*)&p0, *(unsigned int*)&p1);
        ph[lane + 32] = make_uint2(*(unsigned int*)&p2, *(unsigned int*)&p3);
        ph[lane + 64] = make_uint2(*(unsigned int*)&p4, *(unsigned int*)&p5);
        ph[lane + 96] = make_uint2(*(unsigned int*)&p6, *(unsigned int*)&p7);
    }
    __syncthreads();

    // ---- Phase 4: AV via wmma (32t x 64d = 8 warp-tiles of 16x16) ---------------
    {
        const int wm = w >> 2;        // 0..1 (m 16-row half)
        const int wn = w & 3;         // 0..3 (d 16-col quarter)
        wmma::fragment<wmma::accumulator, 16, 16, 16, float> cf;
        wmma::fill_fragment(cf, 0.0f);
        const __half* Vg = g_Vh + (size_t)bh * SS * DH + wn * 16;
#pragma unroll 4
        for (int ks = 0; ks < 32; ks++) {
            wmma::fragment<wmma::matrix_a, 16, 16, 16, __half, wmma::row_major> af;
            wmma::fragment<wmma::matrix_b, 16, 16, 16, __half, wmma::row_major> bf;
            wmma::load_matrix_sync(af, &pH[(wm * 16) * PHP + ks * 16], PHP);
            wmma::load_matrix_sync(bf, Vg + (size_t)ks * 16 * DH, DH);
            wmma::mma_sync(cf, af, bf, cf);
        }
        // C -> sc (reuse as 32 x 68 f32 staging)
        wmma::store_matrix_sync(&sc[(wm * 16) * 68 + wn * 16], cf, 68, wmma::mem_row_major);
    }
    __syncthreads();

    // epilogue: 32 x 64 -> g_attH (fp16)
    {
        const int b = bh >> 2;
        const int mrow = tid >> 3;          // 0..31
        const int d0 = (tid & 7) * 8;       // 0..56
        float4 v0 = *(const float4*)&sc[mrow * 68 + d0];
        float4 v1 = *(const float4*)&sc[mrow * 68 + d0 + 4];
        __half2 h0 = __floats2half2_rn(v0.x, v0.y), h1 = __floats2half2_rn(v0.z, v0.w);
        __half2 h2 = __floats2half2_rn(v1.x, v1.y), h3 = __floats2half2_rn(v1.z, v1.w);
        uint4 u = make_uint4(*(unsigned int*)&h0, *(unsigned int*)&h1,
                             *(unsigned int*)&h2, *(unsigned int*)&h3);
        int t = t0 + mrow;
        *(uint4*)&g_attH[((size_t)(b * TT + t)) * DM + h * DH + d0] = u;
    }
}

// ---------------------------------------------------------------------------
extern "C" void kernel_launch(void* const* d_in, const int* in_sizes, int n_in,
                              void* d_out, int out_size) {
    const float* query = (const float*)d_in[0];
    const float* key   = (const float*)d_in[1];
    const float* value = (const float*)d_in[2];
    const float* w_q   = (const float*)d_in[3];
    const float* w_k   = (const float*)d_in[4];
    const float* w_v   = (const float*)d_in[5];
    const float* v_a   = (const float*)d_in[6];
    const float* w_o   = (const float*)d_in[7];

    float* out  = (float*)d_out;
    float* attn = out + (size_t)BB * TT * DM;

    // Q/K/V projections (tensor cores, double-buffered)
    hgemm_proj<<<dim3(32, 4, 3), 256>>>(query, key, value, w_q, w_k, w_v);

    // fused additive-attention (scores + softmax/attn-write + wmma AV)
    const int dyn = 32 * SCP * sizeof(float) + 32 * PHP * sizeof(__half);  // ~97 KB
    cudaFuncSetAttribute(attn_fused_kernel,
                         cudaFuncAttributeMaxDynamicSharedMemorySize, dyn);
    attn_fused_kernel<<<dim3(BHN, TT / 32), 256, dyn>>>(v_a, attn);

    // output projection (tensor cores, double-buffered)
    hgemm_out<<<dim3(32, 4), 256>>>(w_o, out);
}